// round 2
// baseline (speedup 1.0000x reference)
#include <cuda_runtime.h>

#define N_NODES 100000
#define N_EDGES 3200000
#define CH      128
#define NG      256
#define NC      32

// ---------------- scratch (static device globals; no runtime alloc) ----------------
__device__ float g_y[(size_t)N_NODES * CH];    // xw (layer1) / xw*dinv (layer2)
__device__ float g_h[(size_t)N_NODES * CH];    // layer output
__device__ float g_dinv[N_NODES];
__device__ int   g_deg[N_NODES];
__device__ int   g_rowptr[N_NODES + 1];
__device__ int   g_cursor[N_NODES];
__device__ int   g_csrc[N_EDGES];              // CSR-by-dst source ids
__device__ float g_pool[NG * CH];

// ---------------- CSR construction ----------------
__global__ void init_deg_k() {
    int v = blockIdx.x * blockDim.x + threadIdx.x;
    if (v < N_NODES) g_deg[v] = 1;   // self-loop
}

__global__ void hist_k(const int* __restrict__ dst) {
    int stride = gridDim.x * blockDim.x;
    for (int e = blockIdx.x * blockDim.x + threadIdx.x; e < N_EDGES; e += stride)
        atomicAdd(&g_deg[dst[e]], 1);
}

__global__ void scan_k() {
    __shared__ int ssum[1024];
    const int CHUNK = (N_NODES + 1023) / 1024;   // 98
    int t  = threadIdx.x;
    int lo = t * CHUNK;
    int hi = min(lo + CHUNK, N_NODES);
    int s = 0;
    for (int v = lo; v < hi; v++) s += g_deg[v] - 1;
    ssum[t] = s;
    __syncthreads();
    for (int off = 1; off < 1024; off <<= 1) {
        int val = (t >= off) ? ssum[t - off] : 0;
        __syncthreads();
        ssum[t] += val;
        __syncthreads();
    }
    int run = (t == 0) ? 0 : ssum[t - 1];
    for (int v = lo; v < hi; v++) {
        g_rowptr[v] = run;
        g_cursor[v] = run;
        int d = g_deg[v];
        run += d - 1;
        g_dinv[v] = rsqrtf((float)d);
    }
    if (t == 1023) g_rowptr[N_NODES] = N_EDGES;
}

__global__ void fill_k(const int* __restrict__ src, const int* __restrict__ dst) {
    int stride = gridDim.x * blockDim.x;
    for (int e = blockIdx.x * blockDim.x + threadIdx.x; e < N_EDGES; e += stride) {
        int d = dst[e];
        int p = atomicAdd(&g_cursor[d], 1);
        g_csrc[p] = src[e];
    }
}

// ---------------- GEMM: g_y = (A @ W) [* dinv[row] if FUSE_SCALE] ----------------
// BM=128, BN=128(=CH), 256 threads, 8x8 microtile on packed f32x2 (FFMA2).
// smem: Ws[128][128] floats + As2[8][132] float2 (A values pre-duplicated).
#define GEMM_SMEM (128 * 128 * 4 + 8 * 132 * 8)

__device__ __forceinline__ void ffma2(unsigned long long& acc,
                                      unsigned long long a,
                                      unsigned long long b) {
    asm("fma.rn.f32x2 %0, %1, %2, %0;" : "+l"(acc) : "l"(a), "l"(b));
}

template <int FUSE_SCALE>
__global__ void __launch_bounds__(256, 2) gemm2_k(
    const float* __restrict__ Aext, const float* __restrict__ W, int M)
{
    extern __shared__ float smem[];
    float*  Ws  = smem;                                   // [128*128]
    float2* As2 = (float2*)(smem + 128 * 128);            // [8][132] duplicated pairs

    const float* A = Aext ? Aext : g_h;
    int tid = threadIdx.x;

    // load W (16384 floats) cooperatively
    #pragma unroll
    for (int i = 0; i < 16; i++) {
        int off = tid * 4 + i * 1024;
        *(float4*)&Ws[off] = *(const float4*)&W[off];
    }

    int row0 = blockIdx.x * 128;
    int tx = tid & 15, ty = tid >> 4;

    unsigned long long acc[8][4];   // [row][col-pair] packed f32x2
    #pragma unroll
    for (int i = 0; i < 8; i++)
        #pragma unroll
        for (int j = 0; j < 4; j++) acc[i][j] = 0ull;

    int lr = tid >> 1;            // row within tile this thread loads
    int lc = (tid & 1) * 4;       // 0 or 4
    int grow = row0 + lr;

    for (int kk = 0; kk < CH; kk += 8) {
        float4 av;
        if (grow < M) av = *(const float4*)&A[(size_t)grow * CH + kk + lc];
        else          av = make_float4(0.f, 0.f, 0.f, 0.f);
        __syncthreads();
        As2[(lc + 0) * 132 + lr] = make_float2(av.x, av.x);
        As2[(lc + 1) * 132 + lr] = make_float2(av.y, av.y);
        As2[(lc + 2) * 132 + lr] = make_float2(av.z, av.z);
        As2[(lc + 3) * 132 + lr] = make_float2(av.w, av.w);
        __syncthreads();
        #pragma unroll
        for (int k = 0; k < 8; k++) {
            unsigned long long wv[4], avv[8];
            ulonglong2 w0 = *(ulonglong2*)&Ws[(kk + k) * 128 + tx * 8];
            ulonglong2 w1 = *(ulonglong2*)&Ws[(kk + k) * 128 + tx * 8 + 4];
            wv[0] = w0.x; wv[1] = w0.y; wv[2] = w1.x; wv[3] = w1.y;
            #pragma unroll
            for (int i = 0; i < 4; i++) {
                ulonglong2 t = *(ulonglong2*)&As2[k * 132 + ty * 8 + i * 2];
                avv[2 * i] = t.x; avv[2 * i + 1] = t.y;
            }
            #pragma unroll
            for (int i = 0; i < 8; i++)
                #pragma unroll
                for (int j = 0; j < 4; j++)
                    ffma2(acc[i][j], avv[i], wv[j]);
        }
    }

    #pragma unroll
    for (int i = 0; i < 8; i++) {
        int r = row0 + ty * 8 + i;
        if (r < M) {
            float4 o1 = *(float4*)&acc[i][0];
            float4 o2 = *(float4*)&acc[i][2];
            if (FUSE_SCALE) {
                float dv = g_dinv[r];
                o1.x *= dv; o1.y *= dv; o1.z *= dv; o1.w *= dv;
                o2.x *= dv; o2.y *= dv; o2.z *= dv; o2.w *= dv;
            }
            *(float4*)&g_y[(size_t)r * CH + tx * 8]     = o1;
            *(float4*)&g_y[(size_t)r * CH + tx * 8 + 4] = o2;
        }
    }
}

// ---------------- aggregation ----------------
// PRESCALED=1: y already holds xw*dinv[src] -> h[v] = relu(dinv[v]*(sum y[s] + y[v]) + b)
// PRESCALED=0: y holds raw xw -> gather dinv[s] per edge, self term y[v]*dinv[v]
template <int PRESCALED>
__global__ void __launch_bounds__(256) aggregate_k(const float* __restrict__ bias) {
    int w = (blockIdx.x * blockDim.x + threadIdx.x) >> 5;
    if (w >= N_NODES) return;
    int lane = threadIdx.x & 31;

    const float4* y4 = (const float4*)g_y;
    float dv = g_dinv[w];

    float4 self = y4[(size_t)w * 32 + lane];
    float4 a0, a1;
    if (PRESCALED) {
        a0 = self;
    } else {
        a0.x = self.x * dv; a0.y = self.y * dv;
        a0.z = self.z * dv; a0.w = self.w * dv;
    }
    a1 = make_float4(0.f, 0.f, 0.f, 0.f);

    int beg = g_rowptr[w], end = g_rowptr[w + 1];
    int i = beg;
    for (; i + 32 <= end; i += 32) {
        int idx = g_csrc[i + lane];
        float ds = PRESCALED ? 0.f : g_dinv[idx];
        #pragma unroll
        for (int j = 0; j < 32; j += 2) {
            int s0 = __shfl_sync(0xffffffffu, idx, j);
            int s1 = __shfl_sync(0xffffffffu, idx, j + 1);
            float4 v0 = y4[(size_t)s0 * 32 + lane];
            float4 v1 = y4[(size_t)s1 * 32 + lane];
            if (PRESCALED) {
                a0.x += v0.x; a0.y += v0.y; a0.z += v0.z; a0.w += v0.w;
                a1.x += v1.x; a1.y += v1.y; a1.z += v1.z; a1.w += v1.w;
            } else {
                float d0 = __shfl_sync(0xffffffffu, ds, j);
                float d1 = __shfl_sync(0xffffffffu, ds, j + 1);
                a0.x = fmaf(v0.x, d0, a0.x); a0.y = fmaf(v0.y, d0, a0.y);
                a0.z = fmaf(v0.z, d0, a0.z); a0.w = fmaf(v0.w, d0, a0.w);
                a1.x = fmaf(v1.x, d1, a1.x); a1.y = fmaf(v1.y, d1, a1.y);
                a1.z = fmaf(v1.z, d1, a1.z); a1.w = fmaf(v1.w, d1, a1.w);
            }
        }
    }
    if (i < end) {
        int cnt = end - i;
        int idx = g_csrc[min(i + lane, end - 1)];
        float ds = PRESCALED ? 0.f : g_dinv[idx];
        for (int j = 0; j < cnt; j++) {
            int s = __shfl_sync(0xffffffffu, idx, j);
            float4 v = y4[(size_t)s * 32 + lane];
            if (PRESCALED) {
                a0.x += v.x; a0.y += v.y; a0.z += v.z; a0.w += v.w;
            } else {
                float d0 = __shfl_sync(0xffffffffu, ds, j);
                a0.x = fmaf(v.x, d0, a0.x); a0.y = fmaf(v.y, d0, a0.y);
                a0.z = fmaf(v.z, d0, a0.z); a0.w = fmaf(v.w, d0, a0.w);
            }
        }
    }

    float4 b = ((const float4*)bias)[lane];
    float4 r;
    r.x = fmaxf(fmaf(a0.x + a1.x, dv, b.x), 0.f);
    r.y = fmaxf(fmaf(a0.y + a1.y, dv, b.y), 0.f);
    r.z = fmaxf(fmaf(a0.z + a1.z, dv, b.z), 0.f);
    r.w = fmaxf(fmaf(a0.w + a1.w, dv, b.w), 0.f);
    ((float4*)g_h)[(size_t)w * 32 + lane] = r;
}

// ---------------- pooling + FC ----------------
__device__ __forceinline__ int lower_bound_i(const int* a, int n, int key) {
    int lo = 0, hi = n;
    while (lo < hi) { int mid = (lo + hi) >> 1; if (a[mid] < key) lo = mid + 1; else hi = mid; }
    return lo;
}

__global__ void pool_k(const int* __restrict__ batch) {
    int g = blockIdx.x;
    __shared__ int slo, shi;
    if (threadIdx.x == 0) {
        slo = lower_bound_i(batch, N_NODES, g);
        shi = lower_bound_i(batch, N_NODES, g + 1);
    }
    __syncthreads();
    int lo = slo, hi = shi;
    int c = threadIdx.x;  // 128 threads
    float s = 0.f;
    for (int r = lo; r < hi; r++) s += g_h[(size_t)r * CH + c];
    float cnt = (float)(hi - lo);
    g_pool[g * CH + c] = s / fmaxf(cnt, 1.0f);
}

__global__ void fc_k(const float* __restrict__ Wfc, const float* __restrict__ bfc,
                     float* __restrict__ out) {
    int g = blockIdx.x;
    int c = threadIdx.x;  // 32 threads
    float acc = bfc[c];
    #pragma unroll 4
    for (int k = 0; k < CH; k++)
        acc = fmaf(g_pool[g * CH + k], Wfc[k * NC + c], acc);
    out[g * NC + c] = acc;
}

// ---------------- launcher ----------------
extern "C" void kernel_launch(void* const* d_in, const int* in_sizes, int n_in,
                              void* d_out, int out_size) {
    const float* x     = (const float*)d_in[0];
    const int*   ei    = (const int*)  d_in[1];
    const int*   batch = (const int*)  d_in[2];
    const float* W1    = (const float*)d_in[3];
    const float* b1    = (const float*)d_in[4];
    const float* W2    = (const float*)d_in[5];
    const float* b2    = (const float*)d_in[6];
    const float* Wfc   = (const float*)d_in[7];
    const float* bfc   = (const float*)d_in[8];
    float* out = (float*)d_out;

    const int* src = ei;
    const int* dst = ei + N_EDGES;

    static cudaStream_t s2 = nullptr;
    static cudaEvent_t  e0 = nullptr, e1 = nullptr;
    if (!s2) {
        cudaStreamCreate(&s2);
        cudaEventCreateWithFlags(&e0, cudaEventDisableTiming);
        cudaEventCreateWithFlags(&e1, cudaEventDisableTiming);
        cudaFuncSetAttribute(gemm2_k<0>,
                             cudaFuncAttributeMaxDynamicSharedMemorySize, GEMM_SMEM);
        cudaFuncSetAttribute(gemm2_k<1>,
                             cudaFuncAttributeMaxDynamicSharedMemorySize, GEMM_SMEM);
    }

    int gemm_blocks = (N_NODES + 127) / 128;
    int agg_blocks  = (N_NODES * 32 + 255) / 256;

    // fork: CSR build on s2, layer-1 GEMM (unscaled) on main stream
    cudaEventRecord(e0, 0);
    cudaStreamWaitEvent(s2, e0, 0);

    init_deg_k<<<(N_NODES + 255) / 256, 256, 0, s2>>>();
    hist_k<<<2048, 256, 0, s2>>>(dst);
    scan_k<<<1, 1024, 0, s2>>>();
    fill_k<<<2048, 256, 0, s2>>>(src, dst);

    gemm2_k<0><<<gemm_blocks, 256, GEMM_SMEM>>>(x, W1, N_NODES);

    // join
    cudaEventRecord(e1, s2);
    cudaStreamWaitEvent(0, e1, 0);

    // layer 1 aggregate (per-edge dinv gather)
    aggregate_k<0><<<agg_blocks, 256>>>(b1);
    // layer 2: fused-scale GEMM + prescaled aggregate
    gemm2_k<1><<<gemm_blocks, 256, GEMM_SMEM>>>(nullptr, W2, N_NODES);
    aggregate_k<1><<<agg_blocks, 256>>>(b2);
    // pool + fc
    pool_k<<<NG, 128>>>(batch);
    fc_k<<<NG, NC>>>(Wfc, bfc, out);
}

// round 3
// speedup vs baseline: 1.1052x; 1.1052x over previous
#include <cuda_runtime.h>

#define N_NODES 100000
#define N_EDGES 3200000
#define CH      128
#define NG      256
#define NC      32

// ---------------- scratch (static device globals; no runtime alloc) ----------------
__device__ float g_y[(size_t)N_NODES * CH];    // (x@W)*dinv[row]
__device__ float g_h[(size_t)N_NODES * CH];    // layer output
__device__ float g_dinv[N_NODES];
__device__ int   g_deg[N_NODES];
__device__ int   g_rowptr[N_NODES + 1];
__device__ int   g_cursor[N_NODES];
__device__ int   g_csrc[N_EDGES];              // CSR-by-dst source ids
__device__ float g_pool[NG * CH];

// ---------------- CSR construction ----------------
__global__ void init_deg_k() {
    int v = blockIdx.x * blockDim.x + threadIdx.x;
    if (v < N_NODES) g_deg[v] = 1;   // self-loop
}

__global__ void hist_k(const int* __restrict__ dst) {
    int stride = gridDim.x * blockDim.x;
    for (int e = blockIdx.x * blockDim.x + threadIdx.x; e < N_EDGES; e += stride)
        atomicAdd(&g_deg[dst[e]], 1);
}

__global__ void scan_k() {
    __shared__ int ssum[1024];
    const int CHUNK = (N_NODES + 1023) / 1024;   // 98
    int t  = threadIdx.x;
    int lo = t * CHUNK;
    int hi = min(lo + CHUNK, N_NODES);
    int s = 0;
    for (int v = lo; v < hi; v++) s += g_deg[v] - 1;
    ssum[t] = s;
    __syncthreads();
    for (int off = 1; off < 1024; off <<= 1) {
        int val = (t >= off) ? ssum[t - off] : 0;
        __syncthreads();
        ssum[t] += val;
        __syncthreads();
    }
    int run = (t == 0) ? 0 : ssum[t - 1];
    for (int v = lo; v < hi; v++) {
        g_rowptr[v] = run;
        g_cursor[v] = run;
        int d = g_deg[v];
        run += d - 1;
        g_dinv[v] = rsqrtf((float)d);
    }
    if (t == 1023) g_rowptr[N_NODES] = N_EDGES;
}

__global__ void fill_k(const int* __restrict__ src, const int* __restrict__ dst) {
    int stride = gridDim.x * blockDim.x;
    for (int e = blockIdx.x * blockDim.x + threadIdx.x; e < N_EDGES; e += stride) {
        int d = dst[e];
        int p = atomicAdd(&g_cursor[d], 1);
        g_csrc[p] = src[e];
    }
}

// ---------------- GEMM: g_y = (A @ W) * dinv[row] ----------------
// BM=128, BN=128(=CH), 256 threads, 8x8 microtile.
// FFMA2 (fma.rn.f32x2) inner product; A duplicated into (a,a) pairs IN REGISTERS
// (mov.b64 {r,r}), W pairs read natively from smem as b64. smem layout == R1.
#define GEMM_SMEM ((128 * 128 + 8 * 132) * 4)

__device__ __forceinline__ void ffma2(unsigned long long& acc,
                                      unsigned long long a,
                                      unsigned long long b) {
    asm("fma.rn.f32x2 %0, %1, %2, %0;" : "+l"(acc) : "l"(a), "l"(b));
}

__device__ __forceinline__ unsigned long long dup2(float a) {
    unsigned long long r;
    asm("mov.b64 %0, {%1, %1};" : "=l"(r) : "f"(a));
    return r;
}

__global__ void __launch_bounds__(256, 2) gemm2_k(
    const float* __restrict__ Aext, const float* __restrict__ W, int M)
{
    extern __shared__ float smem[];
    float* Ws = smem;                                       // [128*128]
    float (*As)[132] = (float (*)[132])(smem + 128 * 128);  // [8][132] transposed A tile

    const float* A = Aext ? Aext : g_h;
    int tid = threadIdx.x;

    // load W (16384 floats) cooperatively
    #pragma unroll
    for (int i = 0; i < 16; i++) {
        int off = tid * 4 + i * 1024;
        *(float4*)&Ws[off] = *(const float4*)&W[off];
    }

    int row0 = blockIdx.x * 128;
    int tx = tid & 15, ty = tid >> 4;

    unsigned long long acc[8][4];   // [row][col-pair] packed f32x2
    #pragma unroll
    for (int i = 0; i < 8; i++)
        #pragma unroll
        for (int j = 0; j < 4; j++) acc[i][j] = 0ull;

    int lr = tid >> 1;            // row within tile this thread loads
    int lc = (tid & 1) * 4;       // 0 or 4
    int grow = row0 + lr;

    for (int kk = 0; kk < CH; kk += 8) {
        float4 av;
        if (grow < M) av = *(const float4*)&A[(size_t)grow * CH + kk + lc];
        else          av = make_float4(0.f, 0.f, 0.f, 0.f);
        __syncthreads();
        As[lc + 0][lr] = av.x;
        As[lc + 1][lr] = av.y;
        As[lc + 2][lr] = av.z;
        As[lc + 3][lr] = av.w;
        __syncthreads();
        #pragma unroll
        for (int k = 0; k < 8; k++) {
            // W pairs: natural (w_j, w_{j+1}) layout, two 16B smem loads
            unsigned long long wv[4];
            ulonglong2 w0 = *(ulonglong2*)&Ws[(kk + k) * 128 + tx * 8];
            ulonglong2 w1 = *(ulonglong2*)&Ws[(kk + k) * 128 + tx * 8 + 4];
            wv[0] = w0.x; wv[1] = w0.y; wv[2] = w1.x; wv[3] = w1.y;
            // A: scalar broadcast loads, duplicate in registers
            unsigned long long ad[8];
            #pragma unroll
            for (int i = 0; i < 8; i++) ad[i] = dup2(As[k][ty * 8 + i]);
            #pragma unroll
            for (int i = 0; i < 8; i++)
                #pragma unroll
                for (int j = 0; j < 4; j++)
                    ffma2(acc[i][j], ad[i], wv[j]);
        }
    }

    #pragma unroll
    for (int i = 0; i < 8; i++) {
        int r = row0 + ty * 8 + i;
        if (r < M) {
            float dv = g_dinv[r];
            float4 o1 = *(float4*)&acc[i][0];
            float4 o2 = *(float4*)&acc[i][2];
            o1.x *= dv; o1.y *= dv; o1.z *= dv; o1.w *= dv;
            o2.x *= dv; o2.y *= dv; o2.z *= dv; o2.w *= dv;
            *(float4*)&g_y[(size_t)r * CH + tx * 8]     = o1;
            *(float4*)&g_y[(size_t)r * CH + tx * 8 + 4] = o2;
        }
    }
}

// ---------------- aggregation: g_h[v] = relu(dinv[v]*(sum_{s->v} y[s] + y[v]) + b) ----------------
__global__ void __launch_bounds__(256) aggregate_k(const float* __restrict__ bias) {
    int w = (blockIdx.x * blockDim.x + threadIdx.x) >> 5;
    if (w >= N_NODES) return;
    int lane = threadIdx.x & 31;

    const float4* y4 = (const float4*)g_y;

    float4 a0 = y4[(size_t)w * 32 + lane];   // self-loop term
    float4 a1 = make_float4(0.f, 0.f, 0.f, 0.f);

    int beg = g_rowptr[w], end = g_rowptr[w + 1];
    int i = beg;
    for (; i + 32 <= end; i += 32) {
        int idx = g_csrc[i + lane];
        #pragma unroll
        for (int j = 0; j < 32; j += 2) {
            int s0 = __shfl_sync(0xffffffffu, idx, j);
            int s1 = __shfl_sync(0xffffffffu, idx, j + 1);
            float4 v0 = y4[(size_t)s0 * 32 + lane];
            float4 v1 = y4[(size_t)s1 * 32 + lane];
            a0.x += v0.x; a0.y += v0.y; a0.z += v0.z; a0.w += v0.w;
            a1.x += v1.x; a1.y += v1.y; a1.z += v1.z; a1.w += v1.w;
        }
    }
    if (i < end) {
        int cnt = end - i;
        int idx = g_csrc[min(i + lane, end - 1)];
        for (int j = 0; j < cnt; j++) {
            int s = __shfl_sync(0xffffffffu, idx, j);
            float4 v = y4[(size_t)s * 32 + lane];
            a0.x += v.x; a0.y += v.y; a0.z += v.z; a0.w += v.w;
        }
    }

    float dv = g_dinv[w];
    float4 b = ((const float4*)bias)[lane];
    float4 r;
    r.x = fmaxf(fmaf(a0.x + a1.x, dv, b.x), 0.f);
    r.y = fmaxf(fmaf(a0.y + a1.y, dv, b.y), 0.f);
    r.z = fmaxf(fmaf(a0.z + a1.z, dv, b.z), 0.f);
    r.w = fmaxf(fmaf(a0.w + a1.w, dv, b.w), 0.f);
    ((float4*)g_h)[(size_t)w * 32 + lane] = r;
}

// ---------------- pooling + FC ----------------
__device__ __forceinline__ int lower_bound_i(const int* a, int n, int key) {
    int lo = 0, hi = n;
    while (lo < hi) { int mid = (lo + hi) >> 1; if (a[mid] < key) lo = mid + 1; else hi = mid; }
    return lo;
}

__global__ void pool_k(const int* __restrict__ batch) {
    int g = blockIdx.x;
    __shared__ int slo, shi;
    if (threadIdx.x == 0) {
        slo = lower_bound_i(batch, N_NODES, g);
        shi = lower_bound_i(batch, N_NODES, g + 1);
    }
    __syncthreads();
    int lo = slo, hi = shi;
    int c = threadIdx.x;  // 128 threads
    float s = 0.f;
    for (int r = lo; r < hi; r++) s += g_h[(size_t)r * CH + c];
    float cnt = (float)(hi - lo);
    g_pool[g * CH + c] = s / fmaxf(cnt, 1.0f);
}

__global__ void fc_k(const float* __restrict__ Wfc, const float* __restrict__ bfc,
                     float* __restrict__ out) {
    int g = blockIdx.x;
    int c = threadIdx.x;  // 32 threads
    float acc = bfc[c];
    #pragma unroll 4
    for (int k = 0; k < CH; k++)
        acc = fmaf(g_pool[g * CH + k], Wfc[k * NC + c], acc);
    out[g * NC + c] = acc;
}

// ---------------- launcher (serial, default stream — R1 schedule) ----------------
extern "C" void kernel_launch(void* const* d_in, const int* in_sizes, int n_in,
                              void* d_out, int out_size) {
    const float* x     = (const float*)d_in[0];
    const int*   ei    = (const int*)  d_in[1];
    const int*   batch = (const int*)  d_in[2];
    const float* W1    = (const float*)d_in[3];
    const float* b1    = (const float*)d_in[4];
    const float* W2    = (const float*)d_in[5];
    const float* b2    = (const float*)d_in[6];
    const float* Wfc   = (const float*)d_in[7];
    const float* bfc   = (const float*)d_in[8];
    float* out = (float*)d_out;

    const int* src = ei;
    const int* dst = ei + N_EDGES;

    cudaFuncSetAttribute(gemm2_k,
                         cudaFuncAttributeMaxDynamicSharedMemorySize, GEMM_SMEM);

    // CSR build
    init_deg_k<<<(N_NODES + 255) / 256, 256>>>();
    hist_k<<<2048, 256>>>(dst);
    scan_k<<<1, 1024>>>();
    fill_k<<<2048, 256>>>(src, dst);

    int gemm_blocks = (N_NODES + 127) / 128;
    int agg_blocks  = (N_NODES * 32 + 255) / 256;

    // layer 1
    gemm2_k<<<gemm_blocks, 256, GEMM_SMEM>>>(x, W1, N_NODES);
    aggregate_k<<<agg_blocks, 256>>>(b1);
    // layer 2
    gemm2_k<<<gemm_blocks, 256, GEMM_SMEM>>>(nullptr, W2, N_NODES);
    aggregate_k<<<agg_blocks, 256>>>(b2);
    // pool + fc
    pool_k<<<NG, 128>>>(batch);
    fc_k<<<NG, NC>>>(Wfc, bfc, out);
}

// round 4
// speedup vs baseline: 1.2153x; 1.0996x over previous
#include <cuda_runtime.h>
#include <cuda_fp16.h>

#define N_NODES 100000
#define N_EDGES 3200000
#define CH      128
#define NG      256
#define NC      32

// ---------------- scratch (static device globals; no runtime alloc) ----------------
__device__ __half g_y16[(size_t)N_NODES * CH]; // (x@W)*dinv[row], fp16 gather payload (25.6 MB)
__device__ float  g_h[(size_t)N_NODES * CH];   // layer output, fp32 (51.2 MB)
__device__ float  g_dinv[N_NODES];
__device__ int    g_deg[N_NODES];
__device__ int    g_rowptr[N_NODES + 1];
__device__ int    g_cursor[N_NODES];
__device__ int    g_csrc[N_EDGES];             // CSR-by-dst source ids
__device__ float  g_pool[NG * CH];

// ---------------- CSR construction ----------------
__global__ void init_deg_k() {
    int v = blockIdx.x * blockDim.x + threadIdx.x;
    if (v < N_NODES) g_deg[v] = 1;   // self-loop
}

__global__ void hist_k(const int* __restrict__ dst) {
    int stride = gridDim.x * blockDim.x;
    for (int e = blockIdx.x * blockDim.x + threadIdx.x; e < N_EDGES; e += stride)
        atomicAdd(&g_deg[dst[e]], 1);
}

__global__ void scan_k() {
    __shared__ int ssum[1024];
    const int CHUNK = (N_NODES + 1023) / 1024;   // 98
    int t  = threadIdx.x;
    int lo = t * CHUNK;
    int hi = min(lo + CHUNK, N_NODES);
    int s = 0;
    for (int v = lo; v < hi; v++) s += g_deg[v] - 1;
    ssum[t] = s;
    __syncthreads();
    for (int off = 1; off < 1024; off <<= 1) {
        int val = (t >= off) ? ssum[t - off] : 0;
        __syncthreads();
        ssum[t] += val;
        __syncthreads();
    }
    int run = (t == 0) ? 0 : ssum[t - 1];
    for (int v = lo; v < hi; v++) {
        g_rowptr[v] = run;
        g_cursor[v] = run;
        int d = g_deg[v];
        run += d - 1;
        g_dinv[v] = rsqrtf((float)d);
    }
    if (t == 1023) g_rowptr[N_NODES] = N_EDGES;
}

__global__ void fill_k(const int* __restrict__ src, const int* __restrict__ dst) {
    int stride = gridDim.x * blockDim.x;
    for (int e = blockIdx.x * blockDim.x + threadIdx.x; e < N_EDGES; e += stride) {
        int d = dst[e];
        int p = atomicAdd(&g_cursor[d], 1);
        g_csrc[p] = src[e];
    }
}

// ---------------- GEMM: g_y16 = half((A @ W) * dinv[row]) ----------------
// BM=128, BN=128(=CH), 256 threads, 8x8 microtile, W fully smem-resident.
#define GEMM_SMEM ((128 * 128 + 8 * 132) * 4)

__device__ __forceinline__ void ffma2(unsigned long long& acc,
                                      unsigned long long a,
                                      unsigned long long b) {
    asm("fma.rn.f32x2 %0, %1, %2, %0;" : "+l"(acc) : "l"(a), "l"(b));
}

__device__ __forceinline__ unsigned long long dup2(float a) {
    unsigned long long r;
    asm("mov.b64 %0, {%1, %1};" : "=l"(r) : "f"(a));
    return r;
}

__global__ void __launch_bounds__(256, 2) gemm2_k(
    const float* __restrict__ Aext, const float* __restrict__ W, int M)
{
    extern __shared__ float smem[];
    float* Ws = smem;                                       // [128*128]
    float (*As)[132] = (float (*)[132])(smem + 128 * 128);  // [8][132] transposed A tile

    const float* A = Aext ? Aext : g_h;
    int tid = threadIdx.x;

    // load W (16384 floats) cooperatively
    #pragma unroll
    for (int i = 0; i < 16; i++) {
        int off = tid * 4 + i * 1024;
        *(float4*)&Ws[off] = *(const float4*)&W[off];
    }

    int row0 = blockIdx.x * 128;
    int tx = tid & 15, ty = tid >> 4;

    unsigned long long acc[8][4];   // [row][col-pair] packed f32x2
    #pragma unroll
    for (int i = 0; i < 8; i++)
        #pragma unroll
        for (int j = 0; j < 4; j++) acc[i][j] = 0ull;

    int lr = tid >> 1;            // row within tile this thread loads
    int lc = (tid & 1) * 4;       // 0 or 4
    int grow = row0 + lr;

    for (int kk = 0; kk < CH; kk += 8) {
        float4 av;
        if (grow < M) av = *(const float4*)&A[(size_t)grow * CH + kk + lc];
        else          av = make_float4(0.f, 0.f, 0.f, 0.f);
        __syncthreads();
        As[lc + 0][lr] = av.x;
        As[lc + 1][lr] = av.y;
        As[lc + 2][lr] = av.z;
        As[lc + 3][lr] = av.w;
        __syncthreads();
        #pragma unroll
        for (int k = 0; k < 8; k++) {
            unsigned long long wv[4];
            ulonglong2 w0 = *(ulonglong2*)&Ws[(kk + k) * 128 + tx * 8];
            ulonglong2 w1 = *(ulonglong2*)&Ws[(kk + k) * 128 + tx * 8 + 4];
            wv[0] = w0.x; wv[1] = w0.y; wv[2] = w1.x; wv[3] = w1.y;
            unsigned long long ad[8];
            #pragma unroll
            for (int i = 0; i < 8; i++) ad[i] = dup2(As[k][ty * 8 + i]);
            #pragma unroll
            for (int i = 0; i < 8; i++)
                #pragma unroll
                for (int j = 0; j < 4; j++)
                    ffma2(acc[i][j], ad[i], wv[j]);
        }
    }

    #pragma unroll
    for (int i = 0; i < 8; i++) {
        int r = row0 + ty * 8 + i;
        if (r < M) {
            float dv = g_dinv[r];
            float4 o1 = *(float4*)&acc[i][0];
            float4 o2 = *(float4*)&acc[i][2];
            __half2 p0 = __floats2half2_rn(o1.x * dv, o1.y * dv);
            __half2 p1 = __floats2half2_rn(o1.z * dv, o1.w * dv);
            __half2 p2 = __floats2half2_rn(o2.x * dv, o2.y * dv);
            __half2 p3 = __floats2half2_rn(o2.z * dv, o2.w * dv);
            uint4 pk;
            pk.x = *(unsigned*)&p0; pk.y = *(unsigned*)&p1;
            pk.z = *(unsigned*)&p2; pk.w = *(unsigned*)&p3;
            *(uint4*)&g_y16[(size_t)r * CH + tx * 8] = pk;   // 8 halfs = 16B
        }
    }
}

// ---------------- aggregation: g_h[v] = relu(dinv[v]*(sum_{s->v} y[s] + y[v]) + b) ----------------
// y is fp16; each lane owns 4 channels (uint2 = 4 halfs), accumulates fp32.
__device__ __forceinline__ void acc4(float4& a, uint2 u) {
    float2 f0 = __half22float2(*(__half2*)&u.x);
    float2 f1 = __half22float2(*(__half2*)&u.y);
    a.x += f0.x; a.y += f0.y; a.z += f1.x; a.w += f1.y;
}

__global__ void __launch_bounds__(256) aggregate_k(const float* __restrict__ bias) {
    int w = (blockIdx.x * blockDim.x + threadIdx.x) >> 5;
    if (w >= N_NODES) return;
    int lane = threadIdx.x & 31;

    const uint2* y2 = (const uint2*)g_y16;   // row stride = 32 uint2 (128 halfs)

    float4 a0 = make_float4(0.f, 0.f, 0.f, 0.f);
    float4 a1 = make_float4(0.f, 0.f, 0.f, 0.f);
    acc4(a0, y2[(size_t)w * 32 + lane]);     // self-loop term

    int beg = g_rowptr[w], end = g_rowptr[w + 1];
    int i = beg;
    for (; i + 32 <= end; i += 32) {
        int idx = g_csrc[i + lane];
        #pragma unroll
        for (int j = 0; j < 32; j += 2) {
            int s0 = __shfl_sync(0xffffffffu, idx, j);
            int s1 = __shfl_sync(0xffffffffu, idx, j + 1);
            uint2 u0 = y2[(size_t)s0 * 32 + lane];
            uint2 u1 = y2[(size_t)s1 * 32 + lane];
            acc4(a0, u0);
            acc4(a1, u1);
        }
    }
    if (i < end) {
        int cnt = end - i;
        int idx = g_csrc[min(i + lane, end - 1)];
        for (int j = 0; j < cnt; j++) {
            int s = __shfl_sync(0xffffffffu, idx, j);
            acc4(a0, y2[(size_t)s * 32 + lane]);
        }
    }

    float dv = g_dinv[w];
    float4 b = ((const float4*)bias)[lane];
    float4 r;
    r.x = fmaxf(fmaf(a0.x + a1.x, dv, b.x), 0.f);
    r.y = fmaxf(fmaf(a0.y + a1.y, dv, b.y), 0.f);
    r.z = fmaxf(fmaf(a0.z + a1.z, dv, b.z), 0.f);
    r.w = fmaxf(fmaf(a0.w + a1.w, dv, b.w), 0.f);
    ((float4*)g_h)[(size_t)w * 32 + lane] = r;
}

// ---------------- pooling + FC ----------------
__device__ __forceinline__ int lower_bound_i(const int* a, int n, int key) {
    int lo = 0, hi = n;
    while (lo < hi) { int mid = (lo + hi) >> 1; if (a[mid] < key) lo = mid + 1; else hi = mid; }
    return lo;
}

__global__ void pool_k(const int* __restrict__ batch) {
    int g = blockIdx.x;
    __shared__ int slo, shi;
    if (threadIdx.x == 0) {
        slo = lower_bound_i(batch, N_NODES, g);
        shi = lower_bound_i(batch, N_NODES, g + 1);
    }
    __syncthreads();
    int lo = slo, hi = shi;
    int c = threadIdx.x;  // 128 threads
    float s = 0.f;
    for (int r = lo; r < hi; r++) s += g_h[(size_t)r * CH + c];
    float cnt = (float)(hi - lo);
    g_pool[g * CH + c] = s / fmaxf(cnt, 1.0f);
}

__global__ void fc_k(const float* __restrict__ Wfc, const float* __restrict__ bfc,
                     float* __restrict__ out) {
    int g = blockIdx.x;
    int c = threadIdx.x;  // 32 threads
    float acc = bfc[c];
    #pragma unroll 4
    for (int k = 0; k < CH; k++)
        acc = fmaf(g_pool[g * CH + k], Wfc[k * NC + c], acc);
    out[g * NC + c] = acc;
}

// ---------------- launcher (serial, default stream) ----------------
extern "C" void kernel_launch(void* const* d_in, const int* in_sizes, int n_in,
                              void* d_out, int out_size) {
    const float* x     = (const float*)d_in[0];
    const int*   ei    = (const int*)  d_in[1];
    const int*   batch = (const int*)  d_in[2];
    const float* W1    = (const float*)d_in[3];
    const float* b1    = (const float*)d_in[4];
    const float* W2    = (const float*)d_in[5];
    const float* b2    = (const float*)d_in[6];
    const float* Wfc   = (const float*)d_in[7];
    const float* bfc   = (const float*)d_in[8];
    float* out = (float*)d_out;

    const int* src = ei;
    const int* dst = ei + N_EDGES;

    cudaFuncSetAttribute(gemm2_k,
                         cudaFuncAttributeMaxDynamicSharedMemorySize, GEMM_SMEM);

    // CSR build
    init_deg_k<<<(N_NODES + 255) / 256, 256>>>();
    hist_k<<<2048, 256>>>(dst);
    scan_k<<<1, 1024>>>();
    fill_k<<<2048, 256>>>(src, dst);

    int gemm_blocks = (N_NODES + 127) / 128;
    int agg_blocks  = (N_NODES * 32 + 255) / 256;

    // layer 1
    gemm2_k<<<gemm_blocks, 256, GEMM_SMEM>>>(x, W1, N_NODES);
    aggregate_k<<<agg_blocks, 256>>>(b1);
    // layer 2
    gemm2_k<<<gemm_blocks, 256, GEMM_SMEM>>>(nullptr, W2, N_NODES);
    aggregate_k<<<agg_blocks, 256>>>(b2);
    // pool + fc
    pool_k<<<NG, 128>>>(batch);
    fc_k<<<NG, NC>>>(Wfc, bfc, out);
}

// round 6
// speedup vs baseline: 1.3997x; 1.1518x over previous
#include <cuda_runtime.h>
#include <cuda_fp16.h>
#include <mma.h>

using namespace nvcuda;

#define N_NODES 100000
#define N_EDGES 3200000
#define CH      128
#define NG      256
#define NC      32
#define APAD    136   // half elements per smem row (128 + 8, keeps 16B align, ldm%8==0)

// ---------------- scratch (static device globals; no runtime alloc) ----------------
__device__ __half g_y16[(size_t)N_NODES * CH]; // (x@W)*dinv[row], fp16 (25.6 MB)
__device__ __half g_h[(size_t)N_NODES * CH];   // layer output, fp16 (25.6 MB)
__device__ float  g_dinv[N_NODES];
__device__ int    g_deg[N_NODES];
__device__ int    g_rowptr[N_NODES + 1];
__device__ int    g_cursor[N_NODES];
__device__ int    g_csrc[N_EDGES];             // CSR-by-dst source ids
__device__ float  g_pool[NG * CH];

// ---------------- CSR construction ----------------
__global__ void init_deg_k() {
    int v = blockIdx.x * blockDim.x + threadIdx.x;
    if (v < N_NODES) g_deg[v] = 1;   // self-loop
}

__global__ void hist_k(const int4* __restrict__ dst4) {
    int stride = gridDim.x * blockDim.x;
    for (int e = blockIdx.x * blockDim.x + threadIdx.x; e < N_EDGES / 4; e += stride) {
        int4 d = dst4[e];
        atomicAdd(&g_deg[d.x], 1);
        atomicAdd(&g_deg[d.y], 1);
        atomicAdd(&g_deg[d.z], 1);
        atomicAdd(&g_deg[d.w], 1);
    }
}

__global__ void scan_k() {
    __shared__ int ssum[1024];
    const int CHUNK = (N_NODES + 1023) / 1024;   // 98
    int t  = threadIdx.x;
    int lo = t * CHUNK;
    int hi = min(lo + CHUNK, N_NODES);
    int s = 0;
    for (int v = lo; v < hi; v++) s += g_deg[v] - 1;
    ssum[t] = s;
    __syncthreads();
    for (int off = 1; off < 1024; off <<= 1) {
        int val = (t >= off) ? ssum[t - off] : 0;
        __syncthreads();
        ssum[t] += val;
        __syncthreads();
    }
    int run = (t == 0) ? 0 : ssum[t - 1];
    for (int v = lo; v < hi; v++) {
        g_rowptr[v] = run;
        g_cursor[v] = run;
        int d = g_deg[v];
        run += d - 1;
        g_dinv[v] = rsqrtf((float)d);
    }
    if (t == 1023) g_rowptr[N_NODES] = N_EDGES;
}

__global__ void fill_k(const int4* __restrict__ src4, const int4* __restrict__ dst4) {
    int stride = gridDim.x * blockDim.x;
    for (int e = blockIdx.x * blockDim.x + threadIdx.x; e < N_EDGES / 4; e += stride) {
        int4 s = src4[e];
        int4 d = dst4[e];
        int p0 = atomicAdd(&g_cursor[d.x], 1);
        int p1 = atomicAdd(&g_cursor[d.y], 1);
        int p2 = atomicAdd(&g_cursor[d.z], 1);
        int p3 = atomicAdd(&g_cursor[d.w], 1);
        g_csrc[p0] = s.x;
        g_csrc[p1] = s.y;
        g_csrc[p2] = s.z;
        g_csrc[p3] = s.w;
    }
}

// ---------------- GEMM (tensor core): g_y16 = half((A @ W) * dinv[row]) ----------------
// 128x128 block tile, K=128 fully smem-resident as fp16.
// 8 warps, warp tile 64x32, wmma m16n16k16, fp32 accumulate.
// A_IS_HALF=1 reads g_h (device global) directly inside the kernel.
#define GEMM_SMEM (2 * 128 * APAD * 2)

template <int A_IS_HALF>
__global__ void __launch_bounds__(256) gemm_wmma_k(
    const float* __restrict__ Af, const float* __restrict__ W, int M)
{
    extern __shared__ char smraw[];
    __half* As = (__half*)smraw;                         // [128][APAD]
    __half* Bs = (__half*)(smraw + 128 * APAD * 2);      // [128][APAD], Bs[n][k] = W[k][n]
    float*  Cs = (float*)smraw;                          // [128][128] staging (reused)

    int tid = threadIdx.x;

    // W -> Bs (transpose + convert), 64 elems/thread
    for (int i = tid; i < 128 * 128; i += 256) {
        int k = i >> 7, n = i & 127;
        Bs[n * APAD + k] = __float2half_rn(W[i]);
    }

    // A tile -> As (convert if fp32 source)
    int row0 = blockIdx.x * 128;
    if (A_IS_HALF) {
        const __half* Ah = g_h;   // device-side symbol reference (valid)
        for (int i = tid; i < 128 * 16; i += 256) {      // 16 x uint4 per row
            int r = i >> 4, c8 = i & 15;
            uint4 v = make_uint4(0u, 0u, 0u, 0u);
            if (row0 + r < M) v = *(const uint4*)&Ah[(size_t)(row0 + r) * CH + c8 * 8];
            *(uint4*)&As[r * APAD + c8 * 8] = v;
        }
    } else {
        for (int i = tid; i < 128 * 32; i += 256) {      // 32 x float4 per row
            int r = i >> 5, c4 = i & 31;
            float4 v = make_float4(0.f, 0.f, 0.f, 0.f);
            if (row0 + r < M) v = *(const float4*)&Af[(size_t)(row0 + r) * CH + c4 * 4];
            __half2 h0 = __floats2half2_rn(v.x, v.y);
            __half2 h1 = __floats2half2_rn(v.z, v.w);
            *(uint2*)&As[r * APAD + c4 * 4] =
                make_uint2(*(unsigned*)&h0, *(unsigned*)&h1);
        }
    }
    __syncthreads();

    int wid = tid >> 5;
    int wm = wid >> 2, wn = wid & 3;       // 2 x 4 warp grid
    int wrow = wm * 64, wcol = wn * 32;

    wmma::fragment<wmma::accumulator, 16, 16, 16, float> c[4][2];
    #pragma unroll
    for (int i = 0; i < 4; i++)
        #pragma unroll
        for (int j = 0; j < 2; j++) wmma::fill_fragment(c[i][j], 0.f);

    #pragma unroll
    for (int kk = 0; kk < 128; kk += 16) {
        wmma::fragment<wmma::matrix_a, 16, 16, 16, __half, wmma::row_major> a[4];
        wmma::fragment<wmma::matrix_b, 16, 16, 16, __half, wmma::col_major> b[2];
        #pragma unroll
        for (int i = 0; i < 4; i++)
            wmma::load_matrix_sync(a[i], As + (wrow + i * 16) * APAD + kk, APAD);
        #pragma unroll
        for (int j = 0; j < 2; j++)
            wmma::load_matrix_sync(b[j], Bs + (wcol + j * 16) * APAD + kk, APAD);
        #pragma unroll
        for (int i = 0; i < 4; i++)
            #pragma unroll
            for (int j = 0; j < 2; j++)
                wmma::mma_sync(c[i][j], a[i], b[j], c[i][j]);
    }

    __syncthreads();   // all mma done before As/Bs is overwritten by Cs
    #pragma unroll
    for (int i = 0; i < 4; i++)
        #pragma unroll
        for (int j = 0; j < 2; j++)
            wmma::store_matrix_sync(Cs + (wrow + i * 16) * 128 + wcol + j * 16,
                                    c[i][j], 128, wmma::mem_row_major);
    __syncthreads();

    // scale by dinv[row], convert, store fp16
    for (int i = tid; i < 128 * 16; i += 256) {
        int r = i >> 4, c8 = i & 15;
        int gr = row0 + r;
        if (gr < M) {
            float dv = g_dinv[gr];
            const float* s = &Cs[r * 128 + c8 * 8];
            __half2 p0 = __floats2half2_rn(s[0] * dv, s[1] * dv);
            __half2 p1 = __floats2half2_rn(s[2] * dv, s[3] * dv);
            __half2 p2 = __floats2half2_rn(s[4] * dv, s[5] * dv);
            __half2 p3 = __floats2half2_rn(s[6] * dv, s[7] * dv);
            uint4 pk = make_uint4(*(unsigned*)&p0, *(unsigned*)&p1,
                                  *(unsigned*)&p2, *(unsigned*)&p3);
            *(uint4*)&g_y16[(size_t)gr * CH + c8 * 8] = pk;
        }
    }
}

// ---------------- aggregation: g_h[v] = half(relu(dinv[v]*(sum y[s] + y[v]) + b)) ----------------
__device__ __forceinline__ void acc4(float4& a, uint2 u) {
    float2 f0 = __half22float2(*(__half2*)&u.x);
    float2 f1 = __half22float2(*(__half2*)&u.y);
    a.x += f0.x; a.y += f0.y; a.z += f1.x; a.w += f1.y;
}

__global__ void __launch_bounds__(256) aggregate_k(const float* __restrict__ bias) {
    int w = (blockIdx.x * blockDim.x + threadIdx.x) >> 5;
    if (w >= N_NODES) return;
    int lane = threadIdx.x & 31;

    const uint2* y2 = (const uint2*)g_y16;   // row stride = 32 uint2

    float4 a0 = make_float4(0.f, 0.f, 0.f, 0.f);
    float4 a1 = make_float4(0.f, 0.f, 0.f, 0.f);
    acc4(a0, y2[(size_t)w * 32 + lane]);     // self-loop

    int beg = g_rowptr[w], end = g_rowptr[w + 1];
    int i = beg;
    for (; i + 32 <= end; i += 32) {
        int idx = g_csrc[i + lane];
        #pragma unroll
        for (int j = 0; j < 32; j += 2) {
            int s0 = __shfl_sync(0xffffffffu, idx, j);
            int s1 = __shfl_sync(0xffffffffu, idx, j + 1);
            uint2 u0 = y2[(size_t)s0 * 32 + lane];
            uint2 u1 = y2[(size_t)s1 * 32 + lane];
            acc4(a0, u0);
            acc4(a1, u1);
        }
    }
    if (i < end) {
        int cnt = end - i;
        int idx = g_csrc[min(i + lane, end - 1)];
        for (int j = 0; j < cnt; j++) {
            int s = __shfl_sync(0xffffffffu, idx, j);
            acc4(a0, y2[(size_t)s * 32 + lane]);
        }
    }

    float dv = g_dinv[w];
    float4 b = ((const float4*)bias)[lane];
    float rx = fmaxf(fmaf(a0.x + a1.x, dv, b.x), 0.f);
    float ry = fmaxf(fmaf(a0.y + a1.y, dv, b.y), 0.f);
    float rz = fmaxf(fmaf(a0.z + a1.z, dv, b.z), 0.f);
    float rw = fmaxf(fmaf(a0.w + a1.w, dv, b.w), 0.f);
    __half2 h0 = __floats2half2_rn(rx, ry);
    __half2 h1 = __floats2half2_rn(rz, rw);
    ((uint2*)g_h)[(size_t)w * 32 + lane] =
        make_uint2(*(unsigned*)&h0, *(unsigned*)&h1);
}

// ---------------- pooling + FC ----------------
__device__ __forceinline__ int lower_bound_i(const int* a, int n, int key) {
    int lo = 0, hi = n;
    while (lo < hi) { int mid = (lo + hi) >> 1; if (a[mid] < key) lo = mid + 1; else hi = mid; }
    return lo;
}

__global__ void pool_k(const int* __restrict__ batch) {
    int g = blockIdx.x;
    __shared__ int slo, shi;
    if (threadIdx.x == 0) {
        slo = lower_bound_i(batch, N_NODES, g);
        shi = lower_bound_i(batch, N_NODES, g + 1);
    }
    __syncthreads();
    int lo = slo, hi = shi;
    int c = threadIdx.x;  // 128 threads
    float s = 0.f;
    for (int r = lo; r < hi; r++) s += __half2float(g_h[(size_t)r * CH + c]);
    float cnt = (float)(hi - lo);
    g_pool[g * CH + c] = s / fmaxf(cnt, 1.0f);
}

__global__ void fc_k(const float* __restrict__ Wfc, const float* __restrict__ bfc,
                     float* __restrict__ out) {
    int g = blockIdx.x;
    int c = threadIdx.x;  // 32 threads
    float acc = bfc[c];
    #pragma unroll 4
    for (int k = 0; k < CH; k++)
        acc = fmaf(g_pool[g * CH + k], Wfc[k * NC + c], acc);
    out[g * NC + c] = acc;
}

// ---------------- launcher (serial, default stream) ----------------
extern "C" void kernel_launch(void* const* d_in, const int* in_sizes, int n_in,
                              void* d_out, int out_size) {
    const float* x     = (const float*)d_in[0];
    const int*   ei    = (const int*)  d_in[1];
    const int*   batch = (const int*)  d_in[2];
    const float* W1    = (const float*)d_in[3];
    const float* b1    = (const float*)d_in[4];
    const float* W2    = (const float*)d_in[5];
    const float* b2    = (const float*)d_in[6];
    const float* Wfc   = (const float*)d_in[7];
    const float* bfc   = (const float*)d_in[8];
    float* out = (float*)d_out;

    const int4* src4 = (const int4*)ei;
    const int4* dst4 = (const int4*)(ei + N_EDGES);

    cudaFuncSetAttribute(gemm_wmma_k<0>,
                         cudaFuncAttributeMaxDynamicSharedMemorySize, GEMM_SMEM);
    cudaFuncSetAttribute(gemm_wmma_k<1>,
                         cudaFuncAttributeMaxDynamicSharedMemorySize, GEMM_SMEM);

    // CSR build
    init_deg_k<<<(N_NODES + 255) / 256, 256>>>();
    hist_k<<<1024, 256>>>(dst4);
    scan_k<<<1, 1024>>>();
    fill_k<<<1024, 256>>>(src4, dst4);

    int gemm_blocks = (N_NODES + 127) / 128;
    int agg_blocks  = (N_NODES * 32 + 255) / 256;

    // layer 1 (A = x, fp32, from d_in)
    gemm_wmma_k<0><<<gemm_blocks, 256, GEMM_SMEM>>>(x, W1, N_NODES);
    aggregate_k<<<agg_blocks, 256>>>(b1);
    // layer 2 (A = g_h, fp16, referenced inside the kernel)
    gemm_wmma_k<1><<<gemm_blocks, 256, GEMM_SMEM>>>(nullptr, W2, N_NODES);
    aggregate_k<<<agg_blocks, 256>>>(b2);
    // pool + fc
    pool_k<<<NG, 128>>>(batch);
    fc_k<<<NG, NC>>>(Wfc, bfc, out);
}